// round 14
// baseline (speedup 1.0000x reference)
#include <cuda_runtime.h>
#include <cuda_bf16.h>
#include <cstdint>
#include <cstddef>

#define ROWS   32768
#define NPROJ  3424
#define CONVD  1792
#define DINNER 1536
#define DMODEL 768

typedef unsigned long long ull;

// ---------------- scratch (device globals; no runtime allocation) ----------------
__device__ float g_A1[(size_t)ROWS * NPROJ];            // zxBCdt
__device__ float g_xc[(size_t)ROWS * CONVD];            // conv+silu output
__device__ float g_y [(size_t)4 * ROWS * DINNER];       // per-direction scan outputs
__device__ __nv_bfloat16 g_Uh [(size_t)ROWS * DMODEL];
__device__ __nv_bfloat16 g_Ul [(size_t)ROWS * DMODEL];
__device__ __nv_bfloat16 g_Wih[(size_t)NPROJ * DMODEL];
__device__ __nv_bfloat16 g_Wil[(size_t)NPROJ * DMODEL];
__device__ __nv_bfloat16 g_Woh[(size_t)DMODEL * DINNER];
__device__ __nv_bfloat16 g_Wol[(size_t)DMODEL * DINNER];
__device__ __nv_bfloat16 g_Yh [(size_t)ROWS * DINNER];
__device__ __nv_bfloat16 g_Yl [(size_t)ROWS * DINNER];

// ---------------- packed f32x2 helpers ----------------
__device__ __forceinline__ ull fma2(ull a, ull b, ull c) {
    ull d; asm("fma.rn.f32x2 %0,%1,%2,%3;" : "=l"(d) : "l"(a), "l"(b), "l"(c)); return d;
}
__device__ __forceinline__ ull mul2(ull a, ull b) {
    ull d; asm("mul.rn.f32x2 %0,%1,%2;" : "=l"(d) : "l"(a), "l"(b)); return d;
}
__device__ __forceinline__ ull add2(ull a, ull b) {
    ull d; asm("add.rn.f32x2 %0,%1,%2;" : "=l"(d) : "l"(a), "l"(b)); return d;
}
__device__ __forceinline__ ull pack2(float x) {
    unsigned r = __float_as_uint(x);
    ull d; asm("mov.b64 %0,{%1,%1};" : "=l"(d) : "r"(r)); return d;
}
__device__ __forceinline__ ull pack2f(float x, float y) {
    ull d; asm("mov.b64 %0,{%1,%2};" : "=l"(d)
               : "r"(__float_as_uint(x)), "r"(__float_as_uint(y))); return d;
}

// ---------------- fp32 -> bf16 hi/lo split ----------------
__global__ void cvt_kernel(const float* __restrict__ s,
                           __nv_bfloat16* __restrict__ hi,
                           __nv_bfloat16* __restrict__ lo, size_t n) {
    size_t i = (size_t)blockIdx.x * blockDim.x + threadIdx.x;
    if (i >= n) return;
    float v = s[i];
    __nv_bfloat16 h = __float2bfloat16(v);
    hi[i] = h;
    lo[i] = __float2bfloat16(v - __bfloat162float(h));
}

// =========== tensor-core GEMM (mma.sync): C[M,N] = A[M,K] * B[N,K]^T ===========
// 128x128 CTA tile, KC=32 chunks, 2-stage double buffer, 2 CTAs/SM,
// 3-pass bf16 split (AhBh + AlBh + AhBl), fp32 accumulate.

#define SK 40                            // smem row stride in halves (32 + 8 pad)
#define AR_BYTES (128 * SK * 2)          // 10240 per array
#define STG_BYTES (4 * AR_BYTES)         // 40960 per stage (Ah|Al|Bh|Bl)
#define GEMM_SMEM (2 * STG_BYTES)        // 81920

__device__ __forceinline__ void mma_bf16(float* c, const uint32_t* a, const uint32_t* b) {
    asm volatile("mma.sync.aligned.m16n8k16.row.col.f32.bf16.bf16.f32 "
                 "{%0,%1,%2,%3},{%4,%5,%6,%7},{%8,%9},{%0,%1,%2,%3};"
                 : "+f"(c[0]), "+f"(c[1]), "+f"(c[2]), "+f"(c[3])
                 : "r"(a[0]), "r"(a[1]), "r"(a[2]), "r"(a[3]), "r"(b[0]), "r"(b[1]));
}
__device__ __forceinline__ void ldsm4(uint32_t* r, const __nv_bfloat16* p) {
    uint32_t a = (uint32_t)__cvta_generic_to_shared(p);
    asm volatile("ldmatrix.sync.aligned.m8n8.x4.shared.b16 {%0,%1,%2,%3},[%4];"
                 : "=r"(r[0]), "=r"(r[1]), "=r"(r[2]), "=r"(r[3]) : "r"(a));
}
__device__ __forceinline__ void ldsm2(uint32_t* r, const __nv_bfloat16* p) {
    uint32_t a = (uint32_t)__cvta_generic_to_shared(p);
    asm volatile("ldmatrix.sync.aligned.m8n8.x2.shared.b16 {%0,%1},[%2];"
                 : "=r"(r[0]), "=r"(r[1]) : "r"(a));
}
__device__ __forceinline__ void cpa16(uint32_t dst, const void* src, int sz) {
    asm volatile("cp.async.cg.shared.global [%0], [%1], 16, %2;"
                 :: "r"(dst), "l"(src), "r"(sz));
}

// load one KC=32 chunk into a stage.  256 threads, 2 slots per array each.
__device__ __forceinline__ void load_stage(uint32_t sbase,
        const __nv_bfloat16* __restrict__ Ah, const __nv_bfloat16* __restrict__ Al,
        const __nv_bfloat16* __restrict__ Bh, const __nv_bfloat16* __restrict__ Bl,
        int mBase, int nBase, int N, int K, int k0, int tid)
{
#pragma unroll
    for (int i = 0; i < 2; i++) {
        int idx = tid + i * 256;          // 0..511
        int row = idx >> 2, seg = idx & 3;
        uint32_t so = (uint32_t)(row * (SK * 2) + seg * 16);
        size_t aoff = (size_t)(mBase + row) * K + k0 + seg * 8;
        cpa16(sbase + so,                Ah + aoff, 16);
        cpa16(sbase + AR_BYTES + so,     Al + aoff, 16);
        int brow = nBase + row;
        int ok = (brow < N) ? 16 : 0;
        size_t boff = (size_t)(ok ? brow : 0) * K + k0 + seg * 8;
        cpa16(sbase + 2 * AR_BYTES + so, Bh + boff, ok);
        cpa16(sbase + 3 * AR_BYTES + so, Bl + boff, ok);
    }
    asm volatile("cp.async.commit_group;");
}

__global__ void __launch_bounds__(256, 2)
gemm_bf16x3(const __nv_bfloat16* __restrict__ Ah, const __nv_bfloat16* __restrict__ Al,
            const __nv_bfloat16* __restrict__ Bh, const __nv_bfloat16* __restrict__ Bl,
            float* __restrict__ C, int M, int N, int K)
{
    extern __shared__ char smem[];
    uint32_t sb = (uint32_t)__cvta_generic_to_shared(smem);
    const int tid = threadIdx.x, lane = tid & 31, warp = tid >> 5;
    const int wm = warp >> 2, wn = warp & 3;       // 2x4 warp grid; warp tile 64m x 32n
    const int g = lane >> 2, tg = lane & 3;
    const int mBase = blockIdx.y * 128, nBase = blockIdx.x * 128;

    float acc[4][4][4];
#pragma unroll
    for (int mi = 0; mi < 4; mi++)
#pragma unroll
        for (int ni = 0; ni < 4; ni++)
#pragma unroll
            for (int q = 0; q < 4; q++) acc[mi][ni][q] = 0.f;

    const int KT = K / 32;

    // prologue: both stages in flight
    load_stage(sb,             Ah, Al, Bh, Bl, mBase, nBase, N, K, 0,  tid);
    load_stage(sb + STG_BYTES, Ah, Al, Bh, Bl, mBase, nBase, N, K, 32, tid);

    for (int kt = 0; kt < KT; kt++) {
        const int s = kt & 1;
        if (kt + 1 < KT) asm volatile("cp.async.wait_group 1;" ::: "memory");
        else             asm volatile("cp.async.wait_group 0;" ::: "memory");
        __syncthreads();

        const __nv_bfloat16* sAh = (const __nv_bfloat16*)(smem + s * STG_BYTES);
        const __nv_bfloat16* sAl = (const __nv_bfloat16*)(smem + s * STG_BYTES + AR_BYTES);
        const __nv_bfloat16* sBh = (const __nv_bfloat16*)(smem + s * STG_BYTES + 2 * AR_BYTES);
        const __nv_bfloat16* sBl = (const __nv_bfloat16*)(smem + s * STG_BYTES + 3 * AR_BYTES);

#pragma unroll
        for (int kk = 0; kk < 32; kk += 16) {
            uint32_t aH[4][4], bX[4][2];
            // pass 1: Ah * Bh
#pragma unroll
            for (int mi = 0; mi < 4; mi++) {
                int off = (wm * 64 + mi * 16 + (lane & 15)) * SK + kk + ((lane >> 4) << 3);
                ldsm4(aH[mi], &sAh[off]);
            }
#pragma unroll
            for (int ni = 0; ni < 4; ni++) {
                int off = (wn * 32 + ni * 8 + (lane & 7)) * SK + kk + (((lane >> 3) & 1) << 3);
                ldsm2(bX[ni], &sBh[off]);
            }
#pragma unroll
            for (int mi = 0; mi < 4; mi++)
#pragma unroll
                for (int ni = 0; ni < 4; ni++) mma_bf16(acc[mi][ni], aH[mi], bX[ni]);

            // pass 2: Al * Bh (reuse bX = Bh)
            {
                uint32_t aL[4][4];
#pragma unroll
                for (int mi = 0; mi < 4; mi++) {
                    int off = (wm * 64 + mi * 16 + (lane & 15)) * SK + kk + ((lane >> 4) << 3);
                    ldsm4(aL[mi], &sAl[off]);
                }
#pragma unroll
                for (int mi = 0; mi < 4; mi++)
#pragma unroll
                    for (int ni = 0; ni < 4; ni++) mma_bf16(acc[mi][ni], aL[mi], bX[ni]);
            }

            // pass 3: Ah * Bl (reuse bX regs for Bl)
#pragma unroll
            for (int ni = 0; ni < 4; ni++) {
                int off = (wn * 32 + ni * 8 + (lane & 7)) * SK + kk + (((lane >> 3) & 1) << 3);
                ldsm2(bX[ni], &sBl[off]);
            }
#pragma unroll
            for (int mi = 0; mi < 4; mi++)
#pragma unroll
                for (int ni = 0; ni < 4; ni++) mma_bf16(acc[mi][ni], aH[mi], bX[ni]);
        }
        __syncthreads();

        if (kt + 2 < KT) {
            load_stage(sb + s * STG_BYTES,
                       Ah, Al, Bh, Bl, mBase, nBase, N, K, (kt + 2) * 32, tid);
        }
    }

    // ---- epilogue ----
#pragma unroll
    for (int mi = 0; mi < 4; mi++)
#pragma unroll
        for (int ni = 0; ni < 4; ni++) {
            int row = mBase + wm * 64 + mi * 16 + g;
            int col = nBase + wn * 32 + ni * 8 + tg * 2;
            if (col < N) {
                *(float2*)&C[(size_t)row * N + col] =
                    make_float2(acc[mi][ni][0], acc[mi][ni][1]);
                *(float2*)&C[(size_t)(row + 8) * N + col] =
                    make_float2(acc[mi][ni][2], acc[mi][ni][3]);
            }
        }
}

// ---------------- depthwise 3x3 conv + bias + SiLU ----------------
__global__ void conv_silu(const float* __restrict__ A1, const float* __restrict__ cw,
                          const float* __restrict__ cb, float* __restrict__ xc)
{
    int c = blockIdx.x * 256 + threadIdx.x;   // 0..1791
    int r = blockIdx.y;                        // 0..32767
    int pos = r & 1023;
    int y = pos >> 5, x = pos & 31;
    size_t base = (size_t)(r - pos) * NPROJ;
    float s = cb[c];
#pragma unroll
    for (int dy = 0; dy < 3; dy++) {
        int yy = y + dy - 1;
        if ((unsigned)yy >= 32u) continue;
#pragma unroll
        for (int dx = 0; dx < 3; dx++) {
            int xx = x + dx - 1;
            if ((unsigned)xx >= 32u) continue;
            s += A1[base + (size_t)(yy * 32 + xx) * NPROJ + 1536 + c] * cw[c * 9 + dy * 3 + dx];
        }
    }
    xc[(size_t)r * CONVD + c] = s / (1.f + __expf(-s));
}

// ---------------- selective scan: 2 warps per (dir,b,h), split over P --------------
// Exponential reparameterization with BRANCH-FREE chunked renorm:
//   within a 16-step chunk: es = prod(1+e^dt)  (== e^{sum softplus}),
//   u_j = es_j*dt_j*B_j (staged, lane-parallel over n), Cd_j = (1/es_j)*C_j,
//   hacc += u*x ; y = Cd . hacc      (2 f32x2 per n-pair per step)
//   chunk end: hacc *= 1/es_16 (straight-line, unrolled — no branch in hot loop).
struct Fetch2 { float dt, x; float2 B2, C2; };

__global__ void __launch_bounds__(256)
scan_kernel(const float* __restrict__ A1, const float* __restrict__ xc,
            float* __restrict__ yall)
{
    __shared__ ulonglong2 sSC[8][32];
    const int lane = threadIdx.x & 31, ws = threadIdx.x >> 5;
    const int W = blockIdx.x * 8 + ws;          // 0..6143
    const int scan = W >> 1, ph = W & 1;        // scan id, p-half
    const int k = scan / 768, rem = scan % 768;
    const int b = rem / 24, h = rem % 24;
    const int g = k >> 1, rev = k & 1;
    const size_t rbase = (size_t)b * 1024;
    float* yout = yall + (size_t)k * ROWS * DINNER;

    ull hacc[32];
#pragma unroll
    for (int n = 0; n < 32; n++) hacc[n] = 0ull;

    Fetch2 cur, nxt;
    {
        int tt = rev ? 1023 : 0;
        size_t r = rbase + tt;
        const float* xr = &xc[r * CONVD];
        cur.dt = __ldg(&A1[r * NPROJ + 3328 + k * 24 + h]);
        cur.B2 = *(const float2*)&xr[1536 + g * 64 + lane * 2];
        cur.C2 = *(const float2*)&xr[1664 + g * 64 + lane * 2];
        cur.x  = __ldg(&xr[h * 64 + ph * 32 + lane]);
    }

    for (int c = 0; c < 64; c++) {
        float es = 1.f;
        float eisLast = 1.f;
#pragma unroll
        for (int j = 0; j < 16; j++) {
            const int t = c * 16 + j;
            // clamped prefetch of step t+1 (branch-free)
            {
                int tn = t + 1; if (tn > 1023) tn = 1023;
                int tt = rev ? 1023 - tn : tn;
                size_t r = rbase + tt;
                const float* xr = &xc[r * CONVD];
                nxt.dt = __ldg(&A1[r * NPROJ + 3328 + k * 24 + h]);
                nxt.B2 = *(const float2*)&xr[1536 + g * 64 + lane * 2];
                nxt.C2 = *(const float2*)&xr[1664 + g * 64 + lane * 2];
                nxt.x  = __ldg(&xr[h * 64 + ph * 32 + lane]);
            }
            float e   = __expf(cur.dt);
            float dtp = cur.dt > 20.f ? cur.dt : log1pf(e);
            es *= (1.f + e);                     // e^{s_j}, cumulative product
            float eis  = __frcp_rn(es);          // e^{-s_j}
            float esdt = es * dtp;
            eisLast = eis;
            __syncwarp();
            sSC[ws][lane] = make_ulonglong2(pack2f(esdt * cur.B2.x, esdt * cur.B2.y),
                                            pack2f(eis * cur.C2.x,  eis * cur.C2.y));
            __syncwarp();

            ull x2 = pack2(cur.x);
            ull y0 = 0ull, y1 = 0ull;
#pragma unroll
            for (int m = 0; m < 32; m += 2) {
                ulonglong2 s0 = sSC[ws][m];
                hacc[m] = fma2(s0.x, x2, hacc[m]);
                y0 = fma2(s0.y, hacc[m], y0);
                ulonglong2 s1 = sSC[ws][m + 1];
                hacc[m + 1] = fma2(s1.x, x2, hacc[m + 1]);
                y1 = fma2(s1.y, hacc[m + 1], y1);
            }
            ull ys = add2(y0, y1);
            uint32_t lo, hi;
            asm("mov.b64 {%0,%1},%2;" : "=r"(lo), "=r"(hi) : "l"(ys));
            int tt = rev ? 1023 - t : t;
            yout[(rbase + tt) * DINNER + h * 64 + ph * 32 + lane] =
                __uint_as_float(lo) + __uint_as_float(hi);
            cur = nxt;
        }
        // chunk-boundary renorm (straight-line)
        {
            ull e2 = pack2(eisLast);
#pragma unroll
            for (int m = 0; m < 32; m++) hacc[m] = mul2(hacc[m], e2);
        }
    }
}

// ---------------- sum 4 dirs + gate (silu(z)) + RMSNorm -> bf16 split ----------------
__global__ void __launch_bounds__(256)
gate_rms(const float* __restrict__ A1, const float* __restrict__ yall,
         const float* __restrict__ nw,
         __nv_bfloat16* __restrict__ Yh, __nv_bfloat16* __restrict__ Yl)
{
    __shared__ float red[8];
    __shared__ float s_scale;
    const int r = blockIdx.x, tid = threadIdx.x;
    const float* y0 = yall + (size_t)r * DINNER;
    const float* y1 = y0 + (size_t)ROWS * DINNER;
    const float* y2 = y1 + (size_t)ROWS * DINNER;
    const float* y3 = y2 + (size_t)ROWS * DINNER;

    float v[6]; float ss = 0.f;
#pragma unroll
    for (int i = 0; i < 6; i++) {
        int d = tid + i * 256;
        float y = y0[d] + y1[d] + y2[d] + y3[d];
        float z = A1[(size_t)r * NPROJ + d];
        float zs = z / (1.f + __expf(-z));
        v[i] = y * zs;
        ss += v[i] * v[i];
    }
#pragma unroll
    for (int o = 16; o; o >>= 1) ss += __shfl_xor_sync(0xffffffffu, ss, o);
    if ((tid & 31) == 0) red[tid >> 5] = ss;
    __syncthreads();
    if (tid == 0) {
        float t = 0.f;
#pragma unroll
        for (int i = 0; i < 8; i++) t += red[i];
        s_scale = rsqrtf(t / 1536.f + 1e-5f);
    }
    __syncthreads();
    float scale = s_scale;
#pragma unroll
    for (int i = 0; i < 6; i++) {
        int d = tid + i * 256;
        float yn = v[i] * scale * nw[d];
        __nv_bfloat16 hv = __float2bfloat16(yn);
        size_t idx = (size_t)r * DINNER + d;
        Yh[idx] = hv;
        Yl[idx] = __float2bfloat16(yn - __bfloat162float(hv));
    }
}

// ---------------- host launcher ----------------
extern "C" void kernel_launch(void* const* d_in, const int* in_sizes, int n_in,
                              void* d_out, int out_size)
{
    const float* u      = (const float*)d_in[0];
    const float* w_in   = (const float*)d_in[1];
    const float* conv_w = (const float*)d_in[2];
    const float* conv_b = (const float*)d_in[3];
    const float* norm_w = (const float*)d_in[4];
    const float* w_out  = (const float*)d_in[5];

    void *pA1, *pxc, *py, *pUh, *pUl, *pWih, *pWil, *pWoh, *pWol, *pYh, *pYl;
    cudaGetSymbolAddress(&pA1, g_A1);
    cudaGetSymbolAddress(&pxc, g_xc);
    cudaGetSymbolAddress(&py,  g_y);
    cudaGetSymbolAddress(&pUh, g_Uh);   cudaGetSymbolAddress(&pUl, g_Ul);
    cudaGetSymbolAddress(&pWih, g_Wih); cudaGetSymbolAddress(&pWil, g_Wil);
    cudaGetSymbolAddress(&pWoh, g_Woh); cudaGetSymbolAddress(&pWol, g_Wol);
    cudaGetSymbolAddress(&pYh, g_Yh);   cudaGetSymbolAddress(&pYl, g_Yl);

    cudaFuncSetAttribute(gemm_bf16x3, cudaFuncAttributeMaxDynamicSharedMemorySize, GEMM_SMEM);

    size_t nu  = (size_t)ROWS * DMODEL;
    size_t nwi = (size_t)NPROJ * DMODEL;
    size_t nwo = (size_t)DMODEL * DINNER;
    cvt_kernel<<<(unsigned)((nu  + 255) / 256), 256>>>(u,     (__nv_bfloat16*)pUh,  (__nv_bfloat16*)pUl,  nu);
    cvt_kernel<<<(unsigned)((nwi + 255) / 256), 256>>>(w_in,  (__nv_bfloat16*)pWih, (__nv_bfloat16*)pWil, nwi);
    cvt_kernel<<<(unsigned)((nwo + 255) / 256), 256>>>(w_out, (__nv_bfloat16*)pWoh, (__nv_bfloat16*)pWol, nwo);

    // in-projection: (32768 x 3424) = u (32768 x 768) @ w_in^T
    gemm_bf16x3<<<dim3(27, 256), 256, GEMM_SMEM>>>(
        (__nv_bfloat16*)pUh, (__nv_bfloat16*)pUl,
        (__nv_bfloat16*)pWih, (__nv_bfloat16*)pWil,
        (float*)pA1, ROWS, NPROJ, DMODEL);

    conv_silu<<<dim3(7, ROWS), 256>>>((const float*)pA1, conv_w, conv_b, (float*)pxc);

    scan_kernel<<<768, 256>>>((const float*)pA1, (const float*)pxc, (float*)py);

    gate_rms<<<ROWS, 256>>>((const float*)pA1, (const float*)py, norm_w,
                            (__nv_bfloat16*)pYh, (__nv_bfloat16*)pYl);

    // out-projection: (32768 x 768) = yn (32768 x 1536) @ w_out^T
    gemm_bf16x3<<<dim3(6, 256), 256, GEMM_SMEM>>>(
        (__nv_bfloat16*)pYh, (__nv_bfloat16*)pYl,
        (__nv_bfloat16*)pWoh, (__nv_bfloat16*)pWol,
        (float*)d_out, ROWS, DMODEL, DINNER);
}

// round 16
// speedup vs baseline: 1.2874x; 1.2874x over previous
#include <cuda_runtime.h>
#include <cuda_bf16.h>
#include <cstdint>
#include <cstddef>

#define ROWS   32768
#define NPROJ  3424
#define CONVD  1792
#define DINNER 1536
#define DMODEL 768

typedef unsigned long long ull;

// ---------------- scratch (device globals; no runtime allocation) ----------------
__device__ float g_A1[(size_t)ROWS * NPROJ];            // zxBCdt
__device__ float g_xc[(size_t)ROWS * CONVD];            // conv+silu output
__device__ float g_y [(size_t)4 * ROWS * DINNER];       // per-direction scan outputs
__device__ __nv_bfloat16 g_Uh [(size_t)ROWS * DMODEL];
__device__ __nv_bfloat16 g_Ul [(size_t)ROWS * DMODEL];
__device__ __nv_bfloat16 g_Wih[(size_t)NPROJ * DMODEL];
__device__ __nv_bfloat16 g_Wil[(size_t)NPROJ * DMODEL];
__device__ __nv_bfloat16 g_Woh[(size_t)DMODEL * DINNER];
__device__ __nv_bfloat16 g_Wol[(size_t)DMODEL * DINNER];
__device__ __nv_bfloat16 g_Yh [(size_t)ROWS * DINNER];
__device__ __nv_bfloat16 g_Yl [(size_t)ROWS * DINNER];

// ---------------- packed f32x2 helpers ----------------
__device__ __forceinline__ ull fma2(ull a, ull b, ull c) {
    ull d; asm("fma.rn.f32x2 %0,%1,%2,%3;" : "=l"(d) : "l"(a), "l"(b), "l"(c)); return d;
}
__device__ __forceinline__ ull mul2(ull a, ull b) {
    ull d; asm("mul.rn.f32x2 %0,%1,%2;" : "=l"(d) : "l"(a), "l"(b)); return d;
}
__device__ __forceinline__ ull add2(ull a, ull b) {
    ull d; asm("add.rn.f32x2 %0,%1,%2;" : "=l"(d) : "l"(a), "l"(b)); return d;
}
__device__ __forceinline__ ull pack2(float x) {
    unsigned r = __float_as_uint(x);
    ull d; asm("mov.b64 %0,{%1,%1};" : "=l"(d) : "r"(r)); return d;
}
__device__ __forceinline__ ull pack2f(float x, float y) {
    ull d; asm("mov.b64 %0,{%1,%2};" : "=l"(d)
               : "r"(__float_as_uint(x)), "r"(__float_as_uint(y))); return d;
}

// ---------------- fp32 -> bf16 hi/lo split ----------------
__global__ void cvt_kernel(const float* __restrict__ s,
                           __nv_bfloat16* __restrict__ hi,
                           __nv_bfloat16* __restrict__ lo, size_t n) {
    size_t i = (size_t)blockIdx.x * blockDim.x + threadIdx.x;
    if (i >= n) return;
    float v = s[i];
    __nv_bfloat16 h = __float2bfloat16(v);
    hi[i] = h;
    lo[i] = __float2bfloat16(v - __bfloat162float(h));
}

// =========== tensor-core GEMM (mma.sync): C[M,N] = A[M,K] * B[N,K]^T ===========
// 128x128 CTA tile, KC=32 chunks, 2-stage double buffer, 2 CTAs/SM,
// 3-pass bf16 split (AhBh + AlBh + AhBl), fp32 accumulate.

#define SK 40                            // smem row stride in halves (32 + 8 pad)
#define AR_BYTES (128 * SK * 2)          // 10240 per array
#define STG_BYTES (4 * AR_BYTES)         // 40960 per stage (Ah|Al|Bh|Bl)
#define GEMM_SMEM (2 * STG_BYTES)        // 81920

__device__ __forceinline__ void mma_bf16(float* c, const uint32_t* a, const uint32_t* b) {
    asm volatile("mma.sync.aligned.m16n8k16.row.col.f32.bf16.bf16.f32 "
                 "{%0,%1,%2,%3},{%4,%5,%6,%7},{%8,%9},{%0,%1,%2,%3};"
                 : "+f"(c[0]), "+f"(c[1]), "+f"(c[2]), "+f"(c[3])
                 : "r"(a[0]), "r"(a[1]), "r"(a[2]), "r"(a[3]), "r"(b[0]), "r"(b[1]));
}
__device__ __forceinline__ void ldsm4(uint32_t* r, const __nv_bfloat16* p) {
    uint32_t a = (uint32_t)__cvta_generic_to_shared(p);
    asm volatile("ldmatrix.sync.aligned.m8n8.x4.shared.b16 {%0,%1,%2,%3},[%4];"
                 : "=r"(r[0]), "=r"(r[1]), "=r"(r[2]), "=r"(r[3]) : "r"(a));
}
__device__ __forceinline__ void ldsm2(uint32_t* r, const __nv_bfloat16* p) {
    uint32_t a = (uint32_t)__cvta_generic_to_shared(p);
    asm volatile("ldmatrix.sync.aligned.m8n8.x2.shared.b16 {%0,%1},[%2];"
                 : "=r"(r[0]), "=r"(r[1]) : "r"(a));
}
__device__ __forceinline__ void cpa16(uint32_t dst, const void* src, int sz) {
    asm volatile("cp.async.cg.shared.global [%0], [%1], 16, %2;"
                 :: "r"(dst), "l"(src), "r"(sz));
}

// load one KC=32 chunk into a stage.  256 threads, 2 slots per array each.
__device__ __forceinline__ void load_stage(uint32_t sbase,
        const __nv_bfloat16* __restrict__ Ah, const __nv_bfloat16* __restrict__ Al,
        const __nv_bfloat16* __restrict__ Bh, const __nv_bfloat16* __restrict__ Bl,
        int mBase, int nBase, int N, int K, int k0, int tid)
{
#pragma unroll
    for (int i = 0; i < 2; i++) {
        int idx = tid + i * 256;          // 0..511
        int row = idx >> 2, seg = idx & 3;
        uint32_t so = (uint32_t)(row * (SK * 2) + seg * 16);
        size_t aoff = (size_t)(mBase + row) * K + k0 + seg * 8;
        cpa16(sbase + so,                Ah + aoff, 16);
        cpa16(sbase + AR_BYTES + so,     Al + aoff, 16);
        int brow = nBase + row;
        int ok = (brow < N) ? 16 : 0;
        size_t boff = (size_t)(ok ? brow : 0) * K + k0 + seg * 8;
        cpa16(sbase + 2 * AR_BYTES + so, Bh + boff, ok);
        cpa16(sbase + 3 * AR_BYTES + so, Bl + boff, ok);
    }
    asm volatile("cp.async.commit_group;");
}

__global__ void __launch_bounds__(256, 2)
gemm_bf16x3(const __nv_bfloat16* __restrict__ Ah, const __nv_bfloat16* __restrict__ Al,
            const __nv_bfloat16* __restrict__ Bh, const __nv_bfloat16* __restrict__ Bl,
            float* __restrict__ C, int M, int N, int K)
{
    extern __shared__ char smem[];
    uint32_t sb = (uint32_t)__cvta_generic_to_shared(smem);
    const int tid = threadIdx.x, lane = tid & 31, warp = tid >> 5;
    const int wm = warp >> 2, wn = warp & 3;       // 2x4 warp grid; warp tile 64m x 32n
    const int g = lane >> 2, tg = lane & 3;
    const int mBase = blockIdx.y * 128, nBase = blockIdx.x * 128;

    float acc[4][4][4];
#pragma unroll
    for (int mi = 0; mi < 4; mi++)
#pragma unroll
        for (int ni = 0; ni < 4; ni++)
#pragma unroll
            for (int q = 0; q < 4; q++) acc[mi][ni][q] = 0.f;

    const int KT = K / 32;

    // prologue: both stages in flight
    load_stage(sb,             Ah, Al, Bh, Bl, mBase, nBase, N, K, 0,  tid);
    load_stage(sb + STG_BYTES, Ah, Al, Bh, Bl, mBase, nBase, N, K, 32, tid);

    for (int kt = 0; kt < KT; kt++) {
        const int s = kt & 1;
        if (kt + 1 < KT) asm volatile("cp.async.wait_group 1;" ::: "memory");
        else             asm volatile("cp.async.wait_group 0;" ::: "memory");
        __syncthreads();

        const __nv_bfloat16* sAh = (const __nv_bfloat16*)(smem + s * STG_BYTES);
        const __nv_bfloat16* sAl = (const __nv_bfloat16*)(smem + s * STG_BYTES + AR_BYTES);
        const __nv_bfloat16* sBh = (const __nv_bfloat16*)(smem + s * STG_BYTES + 2 * AR_BYTES);
        const __nv_bfloat16* sBl = (const __nv_bfloat16*)(smem + s * STG_BYTES + 3 * AR_BYTES);

#pragma unroll
        for (int kk = 0; kk < 32; kk += 16) {
            uint32_t aH[4][4], bX[4][2];
            // pass 1: Ah * Bh
#pragma unroll
            for (int mi = 0; mi < 4; mi++) {
                int off = (wm * 64 + mi * 16 + (lane & 15)) * SK + kk + ((lane >> 4) << 3);
                ldsm4(aH[mi], &sAh[off]);
            }
#pragma unroll
            for (int ni = 0; ni < 4; ni++) {
                int off = (wn * 32 + ni * 8 + (lane & 7)) * SK + kk + (((lane >> 3) & 1) << 3);
                ldsm2(bX[ni], &sBh[off]);
            }
#pragma unroll
            for (int mi = 0; mi < 4; mi++)
#pragma unroll
                for (int ni = 0; ni < 4; ni++) mma_bf16(acc[mi][ni], aH[mi], bX[ni]);

            // pass 2: Al * Bh (reuse bX = Bh)
            {
                uint32_t aL[4][4];
#pragma unroll
                for (int mi = 0; mi < 4; mi++) {
                    int off = (wm * 64 + mi * 16 + (lane & 15)) * SK + kk + ((lane >> 4) << 3);
                    ldsm4(aL[mi], &sAl[off]);
                }
#pragma unroll
                for (int mi = 0; mi < 4; mi++)
#pragma unroll
                    for (int ni = 0; ni < 4; ni++) mma_bf16(acc[mi][ni], aL[mi], bX[ni]);
            }

            // pass 3: Ah * Bl (reuse bX regs for Bl)
#pragma unroll
            for (int ni = 0; ni < 4; ni++) {
                int off = (wn * 32 + ni * 8 + (lane & 7)) * SK + kk + (((lane >> 3) & 1) << 3);
                ldsm2(bX[ni], &sBl[off]);
            }
#pragma unroll
            for (int mi = 0; mi < 4; mi++)
#pragma unroll
                for (int ni = 0; ni < 4; ni++) mma_bf16(acc[mi][ni], aH[mi], bX[ni]);
        }
        __syncthreads();

        if (kt + 2 < KT) {
            load_stage(sb + s * STG_BYTES,
                       Ah, Al, Bh, Bl, mBase, nBase, N, K, (kt + 2) * 32, tid);
        }
    }

    // ---- epilogue ----
#pragma unroll
    for (int mi = 0; mi < 4; mi++)
#pragma unroll
        for (int ni = 0; ni < 4; ni++) {
            int row = mBase + wm * 64 + mi * 16 + g;
            int col = nBase + wn * 32 + ni * 8 + tg * 2;
            if (col < N) {
                *(float2*)&C[(size_t)row * N + col] =
                    make_float2(acc[mi][ni][0], acc[mi][ni][1]);
                *(float2*)&C[(size_t)(row + 8) * N + col] =
                    make_float2(acc[mi][ni][2], acc[mi][ni][3]);
            }
        }
}

// ---------------- depthwise 3x3 conv + bias + SiLU ----------------
__global__ void conv_silu(const float* __restrict__ A1, const float* __restrict__ cw,
                          const float* __restrict__ cb, float* __restrict__ xc)
{
    int c = blockIdx.x * 256 + threadIdx.x;   // 0..1791
    int r = blockIdx.y;                        // 0..32767
    int pos = r & 1023;
    int y = pos >> 5, x = pos & 31;
    size_t base = (size_t)(r - pos) * NPROJ;
    float s = cb[c];
#pragma unroll
    for (int dy = 0; dy < 3; dy++) {
        int yy = y + dy - 1;
        if ((unsigned)yy >= 32u) continue;
#pragma unroll
        for (int dx = 0; dx < 3; dx++) {
            int xx = x + dx - 1;
            if ((unsigned)xx >= 32u) continue;
            s += A1[base + (size_t)(yy * 32 + xx) * NPROJ + 1536 + c] * cw[c * 9 + dy * 3 + dx];
        }
    }
    xc[(size_t)r * CONVD + c] = s / (1.f + __expf(-s));
}

// ---------------- selective scan: 2 warps per (dir,b,h), split over P --------------
// R9 arithmetic (h = a*h + B*(dt*x); y = C.h), with:
//  - prefetch depth 2 (cur / n1 / n2 rotation, ~2 steps of DRAM latency cover)
//  - pointer stepping (no per-step index*stride multiplies)
//  - raw B/C staging; dt folded into xd2 (staging independent of softplus MUFUs)
struct Fetch2 { float dt, x; float2 B2, C2; };

__global__ void __launch_bounds__(256)
scan_kernel(const float* __restrict__ A1, const float* __restrict__ xc,
            float* __restrict__ yall)
{
    __shared__ ulonglong2 sSC[8][32];
    const int lane = threadIdx.x & 31, ws = threadIdx.x >> 5;
    const int W = blockIdx.x * 8 + ws;          // 0..6143
    const int scan = W >> 1, ph = W & 1;        // scan id, p-half
    const int k = scan / 768, rem = scan % 768;
    const int b = rem / 24, h = rem % 24;
    const int g = k >> 1, rev = k & 1;
    const size_t rbase = (size_t)b * 1024;
    float* yout = yall + (size_t)k * ROWS * DINNER;

    const int dir = rev ? -1 : 1;
    const int t0  = rev ? 1023 : 0;

    // stepping pointers (advance by dir*stride each step)
    const float* pDt = A1 + (rbase + t0) * NPROJ + 3328 + k * 24 + h;
    const float* pX  = xc + (rbase + t0) * CONVD + h * 64 + ph * 32 + lane;
    const float* pB  = xc + (rbase + t0) * CONVD + 1536 + g * 64 + lane * 2;
    const float* pC  = xc + (rbase + t0) * CONVD + 1664 + g * 64 + lane * 2;
    float*       pY  = yout + (rbase + t0) * DINNER + h * 64 + ph * 32 + lane;
    const ptrdiff_t dA = (ptrdiff_t)dir * NPROJ;
    const ptrdiff_t dX = (ptrdiff_t)dir * CONVD;
    const ptrdiff_t dY = (ptrdiff_t)dir * DINNER;

    ull hst[32];
#pragma unroll
    for (int n = 0; n < 32; n++) hst[n] = 0ull;

    Fetch2 cur, n1, n2;
    // prologue: load t=0 and t=1
    cur.dt = __ldg(pDt); cur.x = __ldg(pX);
    cur.B2 = *(const float2*)pB; cur.C2 = *(const float2*)pC;
    pDt += dA; pX += dX; pB += dX; pC += dX;
    n1.dt = __ldg(pDt); n1.x = __ldg(pX);
    n1.B2 = *(const float2*)pB; n1.C2 = *(const float2*)pC;
    pDt += dA; pX += dX; pB += dX; pC += dX;

    for (int t = 0; t < 1024; t++) {
        // prefetch t+2 (pointers already aimed there; freeze at the end)
        n2.dt = __ldg(pDt); n2.x = __ldg(pX);
        n2.B2 = *(const float2*)pB; n2.C2 = *(const float2*)pC;
        {   // branch-free guarded advance (stop before walking out of range)
            ptrdiff_t sA = (t < 1021) ? dA : 0;
            ptrdiff_t sX = (t < 1021) ? dX : 0;
            pDt += sA; pX += sX; pB += sX; pC += sX;
        }

        // stage raw B/C (independent of the MUFU chain below)
        __syncwarp();
        sSC[ws][lane] = make_ulonglong2(pack2f(cur.B2.x, cur.B2.y),
                                        pack2f(cur.C2.x, cur.C2.y));

        float dtp = cur.dt > 20.f ? cur.dt : log1pf(__expf(cur.dt));
        ull a2  = pack2(__expf(-dtp));
        ull xd2 = pack2(dtp * cur.x);
        __syncwarp();

        ull y0 = 0ull, y1 = 0ull;
#pragma unroll
        for (int m = 0; m < 32; m += 2) {
            ulonglong2 s0 = sSC[ws][m];
            hst[m] = fma2(a2, hst[m], mul2(s0.x, xd2));
            y0 = fma2(s0.y, hst[m], y0);
            ulonglong2 s1 = sSC[ws][m + 1];
            hst[m + 1] = fma2(a2, hst[m + 1], mul2(s1.x, xd2));
            y1 = fma2(s1.y, hst[m + 1], y1);
        }
        ull ys = add2(y0, y1);
        uint32_t lo, hi;
        asm("mov.b64 {%0,%1},%2;" : "=r"(lo), "=r"(hi) : "l"(ys));
        *pY = __uint_as_float(lo) + __uint_as_float(hi);
        pY += dY;

        cur = n1; n1 = n2;
    }
}

// ---------------- sum 4 dirs + gate (silu(z)) + RMSNorm -> bf16 split ----------------
__global__ void __launch_bounds__(256)
gate_rms(const float* __restrict__ A1, const float* __restrict__ yall,
         const float* __restrict__ nw,
         __nv_bfloat16* __restrict__ Yh, __nv_bfloat16* __restrict__ Yl)
{
    __shared__ float red[8];
    __shared__ float s_scale;
    const int r = blockIdx.x, tid = threadIdx.x;
    const float* y0 = yall + (size_t)r * DINNER;
    const float* y1 = y0 + (size_t)ROWS * DINNER;
    const float* y2 = y1 + (size_t)ROWS * DINNER;
    const float* y3 = y2 + (size_t)ROWS * DINNER;

    float v[6]; float ss = 0.f;
#pragma unroll
    for (int i = 0; i < 6; i++) {
        int d = tid + i * 256;
        float y = y0[d] + y1[d] + y2[d] + y3[d];
        float z = A1[(size_t)r * NPROJ + d];
        float zs = z / (1.f + __expf(-z));
        v[i] = y * zs;
        ss += v[i] * v[i];
    }
#pragma unroll
    for (int o = 16; o; o >>= 1) ss += __shfl_xor_sync(0xffffffffu, ss, o);
    if ((tid & 31) == 0) red[tid >> 5] = ss;
    __syncthreads();
    if (tid == 0) {
        float t = 0.f;
#pragma unroll
        for (int i = 0; i < 8; i++) t += red[i];
        s_scale = rsqrtf(t / 1536.f + 1e-5f);
    }
    __syncthreads();
    float scale = s_scale;
#pragma unroll
    for (int i = 0; i < 6; i++) {
        int d = tid + i * 256;
        float yn = v[i] * scale * nw[d];
        __nv_bfloat16 hv = __float2bfloat16(yn);
        size_t idx = (size_t)r * DINNER + d;
        Yh[idx] = hv;
        Yl[idx] = __float2bfloat16(yn - __bfloat162float(hv));
    }
}

// ---------------- host launcher ----------------
extern "C" void kernel_launch(void* const* d_in, const int* in_sizes, int n_in,
                              void* d_out, int out_size)
{
    const float* u      = (const float*)d_in[0];
    const float* w_in   = (const float*)d_in[1];
    const float* conv_w = (const float*)d_in[2];
    const float* conv_b = (const float*)d_in[3];
    const float* norm_w = (const float*)d_in[4];
    const float* w_out  = (const float*)d_in[5];

    void *pA1, *pxc, *py, *pUh, *pUl, *pWih, *pWil, *pWoh, *pWol, *pYh, *pYl;
    cudaGetSymbolAddress(&pA1, g_A1);
    cudaGetSymbolAddress(&pxc, g_xc);
    cudaGetSymbolAddress(&py,  g_y);
    cudaGetSymbolAddress(&pUh, g_Uh);   cudaGetSymbolAddress(&pUl, g_Ul);
    cudaGetSymbolAddress(&pWih, g_Wih); cudaGetSymbolAddress(&pWil, g_Wil);
    cudaGetSymbolAddress(&pWoh, g_Woh); cudaGetSymbolAddress(&pWol, g_Wol);
    cudaGetSymbolAddress(&pYh, g_Yh);   cudaGetSymbolAddress(&pYl, g_Yl);

    cudaFuncSetAttribute(gemm_bf16x3, cudaFuncAttributeMaxDynamicSharedMemorySize, GEMM_SMEM);

    size_t nu  = (size_t)ROWS * DMODEL;
    size_t nwi = (size_t)NPROJ * DMODEL;
    size_t nwo = (size_t)DMODEL * DINNER;
    cvt_kernel<<<(unsigned)((nu  + 255) / 256), 256>>>(u,     (__nv_bfloat16*)pUh,  (__nv_bfloat16*)pUl,  nu);
    cvt_kernel<<<(unsigned)((nwi + 255) / 256), 256>>>(w_in,  (__nv_bfloat16*)pWih, (__nv_bfloat16*)pWil, nwi);
    cvt_kernel<<<(unsigned)((nwo + 255) / 256), 256>>>(w_out, (__nv_bfloat16*)pWoh, (__nv_bfloat16*)pWol, nwo);

    // in-projection: (32768 x 3424) = u (32768 x 768) @ w_in^T
    gemm_bf16x3<<<dim3(27, 256), 256, GEMM_SMEM>>>(
        (__nv_bfloat16*)pUh, (__nv_bfloat16*)pUl,
        (__nv_bfloat16*)pWih, (__nv_bfloat16*)pWil,
        (float*)pA1, ROWS, NPROJ, DMODEL);

    conv_silu<<<dim3(7, ROWS), 256>>>((const float*)pA1, conv_w, conv_b, (float*)pxc);

    scan_kernel<<<768, 256>>>((const float*)pA1, (const float*)pxc, (float*)py);

    gate_rms<<<ROWS, 256>>>((const float*)pA1, (const float*)py, norm_w,
                            (__nv_bfloat16*)pYh, (__nv_bfloat16*)pYl);

    // out-projection: (32768 x 768) = yn (32768 x 1536) @ w_out^T
    gemm_bf16x3<<<dim3(6, 256), 256, GEMM_SMEM>>>(
        (__nv_bfloat16*)pYh, (__nv_bfloat16*)pYl,
        (__nv_bfloat16*)pWoh, (__nv_bfloat16*)pWol,
        (float*)d_out, ROWS, DMODEL, DINNER);
}

// round 17
// speedup vs baseline: 1.2912x; 1.0029x over previous
#include <cuda_runtime.h>
#include <cuda_bf16.h>
#include <cstdint>
#include <cstddef>

#define ROWS   32768
#define NPROJ  3424
#define CONVD  1792
#define DINNER 1536
#define DMODEL 768

typedef unsigned long long ull;

// ---------------- scratch (device globals; no runtime allocation) ----------------
__device__ float g_A1[(size_t)ROWS * NPROJ];            // zxBCdt
__device__ float g_xc[(size_t)ROWS * CONVD];            // conv+silu output
__device__ float g_y [(size_t)4 * ROWS * DINNER];       // per-direction scan outputs
__device__ __nv_bfloat16 g_Uh [(size_t)ROWS * DMODEL];
__device__ __nv_bfloat16 g_Ul [(size_t)ROWS * DMODEL];
__device__ __nv_bfloat16 g_Wih[(size_t)NPROJ * DMODEL];
__device__ __nv_bfloat16 g_Wil[(size_t)NPROJ * DMODEL];
__device__ __nv_bfloat16 g_Woh[(size_t)DMODEL * DINNER];
__device__ __nv_bfloat16 g_Wol[(size_t)DMODEL * DINNER];
__device__ __nv_bfloat16 g_Yh [(size_t)ROWS * DINNER];
__device__ __nv_bfloat16 g_Yl [(size_t)ROWS * DINNER];

// ---------------- packed f32x2 helpers ----------------
__device__ __forceinline__ ull fma2(ull a, ull b, ull c) {
    ull d; asm("fma.rn.f32x2 %0,%1,%2,%3;" : "=l"(d) : "l"(a), "l"(b), "l"(c)); return d;
}
__device__ __forceinline__ ull mul2(ull a, ull b) {
    ull d; asm("mul.rn.f32x2 %0,%1,%2;" : "=l"(d) : "l"(a), "l"(b)); return d;
}
__device__ __forceinline__ ull add2(ull a, ull b) {
    ull d; asm("add.rn.f32x2 %0,%1,%2;" : "=l"(d) : "l"(a), "l"(b)); return d;
}
__device__ __forceinline__ ull pack2(float x) {
    unsigned r = __float_as_uint(x);
    ull d; asm("mov.b64 %0,{%1,%1};" : "=l"(d) : "r"(r)); return d;
}
__device__ __forceinline__ ull pack2f(float x, float y) {
    ull d; asm("mov.b64 %0,{%1,%2};" : "=l"(d)
               : "r"(__float_as_uint(x)), "r"(__float_as_uint(y))); return d;
}

// ---------------- fp32 -> bf16 hi/lo split ----------------
__global__ void cvt_kernel(const float* __restrict__ s,
                           __nv_bfloat16* __restrict__ hi,
                           __nv_bfloat16* __restrict__ lo, size_t n) {
    size_t i = (size_t)blockIdx.x * blockDim.x + threadIdx.x;
    if (i >= n) return;
    float v = s[i];
    __nv_bfloat16 h = __float2bfloat16(v);
    hi[i] = h;
    lo[i] = __float2bfloat16(v - __bfloat162float(h));
}

// =========== tensor-core GEMM (mma.sync): C[M,N] = A[M,K] * B[N,K]^T ===========
// 128x128 CTA tile, KC=32 chunks, 2-stage double buffer, 2 CTAs/SM,
// 3-pass bf16 split (AhBh + AlBh + AhBl), fp32 accumulate.

#define SK 40                            // smem row stride in halves (32 + 8 pad)
#define AR_BYTES (128 * SK * 2)          // 10240 per array
#define STG_BYTES (4 * AR_BYTES)         // 40960 per stage (Ah|Al|Bh|Bl)
#define GEMM_SMEM (2 * STG_BYTES)        // 81920

__device__ __forceinline__ void mma_bf16(float* c, const uint32_t* a, const uint32_t* b) {
    asm volatile("mma.sync.aligned.m16n8k16.row.col.f32.bf16.bf16.f32 "
                 "{%0,%1,%2,%3},{%4,%5,%6,%7},{%8,%9},{%0,%1,%2,%3};"
                 : "+f"(c[0]), "+f"(c[1]), "+f"(c[2]), "+f"(c[3])
                 : "r"(a[0]), "r"(a[1]), "r"(a[2]), "r"(a[3]), "r"(b[0]), "r"(b[1]));
}
__device__ __forceinline__ void ldsm4(uint32_t* r, const __nv_bfloat16* p) {
    uint32_t a = (uint32_t)__cvta_generic_to_shared(p);
    asm volatile("ldmatrix.sync.aligned.m8n8.x4.shared.b16 {%0,%1,%2,%3},[%4];"
                 : "=r"(r[0]), "=r"(r[1]), "=r"(r[2]), "=r"(r[3]) : "r"(a));
}
__device__ __forceinline__ void ldsm2(uint32_t* r, const __nv_bfloat16* p) {
    uint32_t a = (uint32_t)__cvta_generic_to_shared(p);
    asm volatile("ldmatrix.sync.aligned.m8n8.x2.shared.b16 {%0,%1},[%2];"
                 : "=r"(r[0]), "=r"(r[1]) : "r"(a));
}
__device__ __forceinline__ void cpa16(uint32_t dst, const void* src, int sz) {
    asm volatile("cp.async.cg.shared.global [%0], [%1], 16, %2;"
                 :: "r"(dst), "l"(src), "r"(sz));
}

// load one KC=32 chunk into a stage.  256 threads, 2 slots per array each.
__device__ __forceinline__ void load_stage(uint32_t sbase,
        const __nv_bfloat16* __restrict__ Ah, const __nv_bfloat16* __restrict__ Al,
        const __nv_bfloat16* __restrict__ Bh, const __nv_bfloat16* __restrict__ Bl,
        int mBase, int nBase, int N, int K, int k0, int tid)
{
#pragma unroll
    for (int i = 0; i < 2; i++) {
        int idx = tid + i * 256;          // 0..511
        int row = idx >> 2, seg = idx & 3;
        uint32_t so = (uint32_t)(row * (SK * 2) + seg * 16);
        size_t aoff = (size_t)(mBase + row) * K + k0 + seg * 8;
        cpa16(sbase + so,                Ah + aoff, 16);
        cpa16(sbase + AR_BYTES + so,     Al + aoff, 16);
        int brow = nBase + row;
        int ok = (brow < N) ? 16 : 0;
        size_t boff = (size_t)(ok ? brow : 0) * K + k0 + seg * 8;
        cpa16(sbase + 2 * AR_BYTES + so, Bh + boff, ok);
        cpa16(sbase + 3 * AR_BYTES + so, Bl + boff, ok);
    }
    asm volatile("cp.async.commit_group;");
}

__global__ void __launch_bounds__(256, 2)
gemm_bf16x3(const __nv_bfloat16* __restrict__ Ah, const __nv_bfloat16* __restrict__ Al,
            const __nv_bfloat16* __restrict__ Bh, const __nv_bfloat16* __restrict__ Bl,
            float* __restrict__ C, int M, int N, int K)
{
    extern __shared__ char smem[];
    uint32_t sb = (uint32_t)__cvta_generic_to_shared(smem);
    const int tid = threadIdx.x, lane = tid & 31, warp = tid >> 5;
    const int wm = warp >> 2, wn = warp & 3;       // 2x4 warp grid; warp tile 64m x 32n
    const int g = lane >> 2, tg = lane & 3;
    const int mBase = blockIdx.y * 128, nBase = blockIdx.x * 128;

    float acc[4][4][4];
#pragma unroll
    for (int mi = 0; mi < 4; mi++)
#pragma unroll
        for (int ni = 0; ni < 4; ni++)
#pragma unroll
            for (int q = 0; q < 4; q++) acc[mi][ni][q] = 0.f;

    const int KT = K / 32;

    // prologue: both stages in flight
    load_stage(sb,             Ah, Al, Bh, Bl, mBase, nBase, N, K, 0,  tid);
    load_stage(sb + STG_BYTES, Ah, Al, Bh, Bl, mBase, nBase, N, K, 32, tid);

    for (int kt = 0; kt < KT; kt++) {
        const int s = kt & 1;
        if (kt + 1 < KT) asm volatile("cp.async.wait_group 1;" ::: "memory");
        else             asm volatile("cp.async.wait_group 0;" ::: "memory");
        __syncthreads();

        const __nv_bfloat16* sAh = (const __nv_bfloat16*)(smem + s * STG_BYTES);
        const __nv_bfloat16* sAl = (const __nv_bfloat16*)(smem + s * STG_BYTES + AR_BYTES);
        const __nv_bfloat16* sBh = (const __nv_bfloat16*)(smem + s * STG_BYTES + 2 * AR_BYTES);
        const __nv_bfloat16* sBl = (const __nv_bfloat16*)(smem + s * STG_BYTES + 3 * AR_BYTES);

#pragma unroll
        for (int kk = 0; kk < 32; kk += 16) {
            uint32_t aH[4][4], bX[4][2];
            // pass 1: Ah * Bh
#pragma unroll
            for (int mi = 0; mi < 4; mi++) {
                int off = (wm * 64 + mi * 16 + (lane & 15)) * SK + kk + ((lane >> 4) << 3);
                ldsm4(aH[mi], &sAh[off]);
            }
#pragma unroll
            for (int ni = 0; ni < 4; ni++) {
                int off = (wn * 32 + ni * 8 + (lane & 7)) * SK + kk + (((lane >> 3) & 1) << 3);
                ldsm2(bX[ni], &sBh[off]);
            }
#pragma unroll
            for (int mi = 0; mi < 4; mi++)
#pragma unroll
                for (int ni = 0; ni < 4; ni++) mma_bf16(acc[mi][ni], aH[mi], bX[ni]);

            // pass 2: Al * Bh (reuse bX = Bh)
            {
                uint32_t aL[4][4];
#pragma unroll
                for (int mi = 0; mi < 4; mi++) {
                    int off = (wm * 64 + mi * 16 + (lane & 15)) * SK + kk + ((lane >> 4) << 3);
                    ldsm4(aL[mi], &sAl[off]);
                }
#pragma unroll
                for (int mi = 0; mi < 4; mi++)
#pragma unroll
                    for (int ni = 0; ni < 4; ni++) mma_bf16(acc[mi][ni], aL[mi], bX[ni]);
            }

            // pass 3: Ah * Bl (reuse bX regs for Bl)
#pragma unroll
            for (int ni = 0; ni < 4; ni++) {
                int off = (wn * 32 + ni * 8 + (lane & 7)) * SK + kk + (((lane >> 3) & 1) << 3);
                ldsm2(bX[ni], &sBl[off]);
            }
#pragma unroll
            for (int mi = 0; mi < 4; mi++)
#pragma unroll
                for (int ni = 0; ni < 4; ni++) mma_bf16(acc[mi][ni], aH[mi], bX[ni]);
        }
        __syncthreads();

        if (kt + 2 < KT) {
            load_stage(sb + s * STG_BYTES,
                       Ah, Al, Bh, Bl, mBase, nBase, N, K, (kt + 2) * 32, tid);
        }
    }

    // ---- epilogue ----
#pragma unroll
    for (int mi = 0; mi < 4; mi++)
#pragma unroll
        for (int ni = 0; ni < 4; ni++) {
            int row = mBase + wm * 64 + mi * 16 + g;
            int col = nBase + wn * 32 + ni * 8 + tg * 2;
            if (col < N) {
                *(float2*)&C[(size_t)row * N + col] =
                    make_float2(acc[mi][ni][0], acc[mi][ni][1]);
                *(float2*)&C[(size_t)(row + 8) * N + col] =
                    make_float2(acc[mi][ni][2], acc[mi][ni][3]);
            }
        }
}

// ---------------- depthwise 3x3 conv + bias + SiLU ----------------
__global__ void conv_silu(const float* __restrict__ A1, const float* __restrict__ cw,
                          const float* __restrict__ cb, float* __restrict__ xc)
{
    int c = blockIdx.x * 256 + threadIdx.x;   // 0..1791
    int r = blockIdx.y;                        // 0..32767
    int pos = r & 1023;
    int y = pos >> 5, x = pos & 31;
    size_t base = (size_t)(r - pos) * NPROJ;
    float s = cb[c];
#pragma unroll
    for (int dy = 0; dy < 3; dy++) {
        int yy = y + dy - 1;
        if ((unsigned)yy >= 32u) continue;
#pragma unroll
        for (int dx = 0; dx < 3; dx++) {
            int xx = x + dx - 1;
            if ((unsigned)xx >= 32u) continue;
            s += A1[base + (size_t)(yy * 32 + xx) * NPROJ + 1536 + c] * cw[c * 9 + dy * 3 + dx];
        }
    }
    xc[(size_t)r * CONVD + c] = s / (1.f + __expf(-s));
}

// ---------------- selective scan: 2 warps per (dir,b,h), split over P --------------
// R9 arithmetic (h = a*h + B*(dt*x); y = C.h), with:
//  - prefetch depth 3 (cur / n1 / n2 / n3 rotation)
//  - pointer stepping (no per-step index*stride multiplies)
//  - 3-slot rotating staging buffer, ONE syncwarp per step
struct Fetch2 { float dt, x; float2 B2, C2; };

__global__ void __launch_bounds__(256, 2)
scan_kernel(const float* __restrict__ A1, const float* __restrict__ xc,
            float* __restrict__ yall)
{
    __shared__ ulonglong2 sSC[8][3][32];      // 8 warps x 3 slots x 32 n-pairs
    const int lane = threadIdx.x & 31, ws = threadIdx.x >> 5;
    const int W = blockIdx.x * 8 + ws;          // 0..6143
    const int scan = W >> 1, ph = W & 1;        // scan id, p-half
    const int k = scan / 768, rem = scan % 768;
    const int b = rem / 24, h = rem % 24;
    const int g = k >> 1, rev = k & 1;
    const size_t rbase = (size_t)b * 1024;
    float* yout = yall + (size_t)k * ROWS * DINNER;

    const int dir = rev ? -1 : 1;
    const int t0  = rev ? 1023 : 0;

    // stepping pointers (advance by dir*stride each step)
    const float* pDt = A1 + (rbase + t0) * NPROJ + 3328 + k * 24 + h;
    const float* pX  = xc + (rbase + t0) * CONVD + h * 64 + ph * 32 + lane;
    const float* pB  = xc + (rbase + t0) * CONVD + 1536 + g * 64 + lane * 2;
    const float* pC  = xc + (rbase + t0) * CONVD + 1664 + g * 64 + lane * 2;
    float*       pY  = yout + (rbase + t0) * DINNER + h * 64 + ph * 32 + lane;
    const ptrdiff_t dA = (ptrdiff_t)dir * NPROJ;
    const ptrdiff_t dX = (ptrdiff_t)dir * CONVD;
    const ptrdiff_t dY = (ptrdiff_t)dir * DINNER;

    ull hst[32];
#pragma unroll
    for (int n = 0; n < 32; n++) hst[n] = 0ull;

    Fetch2 cur, n1, n2, n3;
    // prologue: load t=0,1,2
    cur.dt = __ldg(pDt); cur.x = __ldg(pX);
    cur.B2 = *(const float2*)pB; cur.C2 = *(const float2*)pC;
    pDt += dA; pX += dX; pB += dX; pC += dX;
    n1.dt = __ldg(pDt); n1.x = __ldg(pX);
    n1.B2 = *(const float2*)pB; n1.C2 = *(const float2*)pC;
    pDt += dA; pX += dX; pB += dX; pC += dX;
    n2.dt = __ldg(pDt); n2.x = __ldg(pX);
    n2.B2 = *(const float2*)pB; n2.C2 = *(const float2*)pC;
    pDt += dA; pX += dX; pB += dX; pC += dX;

    // stage step 0 into slot 0
    sSC[ws][0][lane] = make_ulonglong2(pack2f(cur.B2.x, cur.B2.y),
                                       pack2f(cur.C2.x, cur.C2.y));
    __syncwarp();

    int slotW = 1;   // slot to write (for step t+1)
    int slotR = 0;   // slot to read (step t)
    for (int t = 0; t < 1024; t++) {
        // prefetch t+3 (pointers already aimed; freeze at range end)
        n3.dt = __ldg(pDt); n3.x = __ldg(pX);
        n3.B2 = *(const float2*)pB; n3.C2 = *(const float2*)pC;
        {
            ptrdiff_t sA = (t < 1020) ? dA : 0;
            ptrdiff_t sX = (t < 1020) ? dX : 0;
            pDt += sA; pX += sX; pB += sX; pC += sX;
        }

        // stage step t+1's raw B/C into the write slot
        sSC[ws][slotW][lane] = make_ulonglong2(pack2f(n1.B2.x, n1.B2.y),
                                               pack2f(n1.C2.x, n1.C2.y));

        float dtp = cur.dt > 20.f ? cur.dt : log1pf(__expf(cur.dt));
        ull a2  = pack2(__expf(-dtp));
        ull xd2 = pack2(dtp * cur.x);
        __syncwarp();       // single sync: write slotW done, read slotR safe

        const ulonglong2* bc = sSC[ws][slotR];
        ull y0 = 0ull, y1 = 0ull;
#pragma unroll
        for (int m = 0; m < 32; m += 2) {
            ulonglong2 s0 = bc[m];
            hst[m] = fma2(a2, hst[m], mul2(s0.x, xd2));
            y0 = fma2(s0.y, hst[m], y0);
            ulonglong2 s1 = bc[m + 1];
            hst[m + 1] = fma2(a2, hst[m + 1], mul2(s1.x, xd2));
            y1 = fma2(s1.y, hst[m + 1], y1);
        }
        ull ys = add2(y0, y1);
        uint32_t lo, hi;
        asm("mov.b64 {%0,%1},%2;" : "=r"(lo), "=r"(hi) : "l"(ys));
        *pY = __uint_as_float(lo) + __uint_as_float(hi);
        pY += dY;

        cur = n1; n1 = n2; n2 = n3;
        slotR = slotW;
        slotW = (slotW == 2) ? 0 : slotW + 1;
    }
}

// ---------------- sum 4 dirs + gate (silu(z)) + RMSNorm -> bf16 split ----------------
__global__ void __launch_bounds__(256)
gate_rms(const float* __restrict__ A1, const float* __restrict__ yall,
         const float* __restrict__ nw,
         __nv_bfloat16* __restrict__ Yh, __nv_bfloat16* __restrict__ Yl)
{
    __shared__ float red[8];
    __shared__ float s_scale;
    const int r = blockIdx.x, tid = threadIdx.x;
    const float* y0 = yall + (size_t)r * DINNER;
    const float* y1 = y0 + (size_t)ROWS * DINNER;
    const float* y2 = y1 + (size_t)ROWS * DINNER;
    const float* y3 = y2 + (size_t)ROWS * DINNER;

    float v[6]; float ss = 0.f;
#pragma unroll
    for (int i = 0; i < 6; i++) {
        int d = tid + i * 256;
        float y = y0[d] + y1[d] + y2[d] + y3[d];
        float z = A1[(size_t)r * NPROJ + d];
        float zs = z / (1.f + __expf(-z));
        v[i] = y * zs;
        ss += v[i] * v[i];
    }
#pragma unroll
    for (int o = 16; o; o >>= 1) ss += __shfl_xor_sync(0xffffffffu, ss, o);
    if ((tid & 31) == 0) red[tid >> 5] = ss;
    __syncthreads();
    if (tid == 0) {
        float t = 0.f;
#pragma unroll
        for (int i = 0; i < 8; i++) t += red[i];
        s_scale = rsqrtf(t / 1536.f + 1e-5f);
    }
    __syncthreads();
    float scale = s_scale;
#pragma unroll
    for (int i = 0; i < 6; i++) {
        int d = tid + i * 256;
        float yn = v[i] * scale * nw[d];
        __nv_bfloat16 hv = __float2bfloat16(yn);
        size_t idx = (size_t)r * DINNER + d;
        Yh[idx] = hv;
        Yl[idx] = __float2bfloat16(yn - __bfloat162float(hv));
    }
}

// ---------------- host launcher ----------------
extern "C" void kernel_launch(void* const* d_in, const int* in_sizes, int n_in,
                              void* d_out, int out_size)
{
    const float* u      = (const float*)d_in[0];
    const float* w_in   = (const float*)d_in[1];
    const float* conv_w = (const float*)d_in[2];
    const float* conv_b = (const float*)d_in[3];
    const float* norm_w = (const float*)d_in[4];
    const float* w_out  = (const float*)d_in[5];

    void *pA1, *pxc, *py, *pUh, *pUl, *pWih, *pWil, *pWoh, *pWol, *pYh, *pYl;
    cudaGetSymbolAddress(&pA1, g_A1);
    cudaGetSymbolAddress(&pxc, g_xc);
    cudaGetSymbolAddress(&py,  g_y);
    cudaGetSymbolAddress(&pUh, g_Uh);   cudaGetSymbolAddress(&pUl, g_Ul);
    cudaGetSymbolAddress(&pWih, g_Wih); cudaGetSymbolAddress(&pWil, g_Wil);
    cudaGetSymbolAddress(&pWoh, g_Woh); cudaGetSymbolAddress(&pWol, g_Wol);
    cudaGetSymbolAddress(&pYh, g_Yh);   cudaGetSymbolAddress(&pYl, g_Yl);

    cudaFuncSetAttribute(gemm_bf16x3, cudaFuncAttributeMaxDynamicSharedMemorySize, GEMM_SMEM);

    size_t nu  = (size_t)ROWS * DMODEL;
    size_t nwi = (size_t)NPROJ * DMODEL;
    size_t nwo = (size_t)DMODEL * DINNER;
    cvt_kernel<<<(unsigned)((nu  + 255) / 256), 256>>>(u,     (__nv_bfloat16*)pUh,  (__nv_bfloat16*)pUl,  nu);
    cvt_kernel<<<(unsigned)((nwi + 255) / 256), 256>>>(w_in,  (__nv_bfloat16*)pWih, (__nv_bfloat16*)pWil, nwi);
    cvt_kernel<<<(unsigned)((nwo + 255) / 256), 256>>>(w_out, (__nv_bfloat16*)pWoh, (__nv_bfloat16*)pWol, nwo);

    // in-projection: (32768 x 3424) = u (32768 x 768) @ w_in^T
    gemm_bf16x3<<<dim3(27, 256), 256, GEMM_SMEM>>>(
        (__nv_bfloat16*)pUh, (__nv_bfloat16*)pUl,
        (__nv_bfloat16*)pWih, (__nv_bfloat16*)pWil,
        (float*)pA1, ROWS, NPROJ, DMODEL);

    conv_silu<<<dim3(7, ROWS), 256>>>((const float*)pA1, conv_w, conv_b, (float*)pxc);

    scan_kernel<<<768, 256>>>((const float*)pA1, (const float*)pxc, (float*)py);

    gate_rms<<<ROWS, 256>>>((const float*)pA1, (const float*)py, norm_w,
                            (__nv_bfloat16*)pYh, (__nv_bfloat16*)pYl);

    // out-projection: (32768 x 768) = yn (32768 x 1536) @ w_out^T
    gemm_bf16x3<<<dim3(6, 256), 256, GEMM_SMEM>>>(
        (__nv_bfloat16*)pYh, (__nv_bfloat16*)pYl,
        (__nv_bfloat16*)pWoh, (__nv_bfloat16*)pWol,
        (float*)d_out, ROWS, DMODEL, DINNER);
}